// round 1
// baseline (speedup 1.0000x reference)
#include <cuda_runtime.h>

#define SEQ   2048
#define BATCH 2
#define NH    16
#define DH    64
#define DM    1024
#define MTOT  (BATCH*SEQ)   // 4096 rows

// Scratch (device globals: no allocation allowed in kernel_launch)
__device__ float g_q[(size_t)MTOT * DM];
__device__ float g_k[(size_t)MTOT * DM];
__device__ float g_v[(size_t)MTOT * DM];
__device__ float g_z[(size_t)MTOT * DM];

// ---------------------------------------------------------------------------
// SGEMM: C[4096,1024] = A[4096,1024] @ W + bias
//   MODE 0: W index = k*1024 + n                       (W_O  [h*64+d, m] row-major)
//   MODE 1: W index = (n>>6)*65536 + k*64 + (n&63)     (W_Q/K/V [h, m, d])
// 128x128 tile, BK=8, 8x8 per thread (split 4+4), 256 threads.
// ---------------------------------------------------------------------------
template<int MODE>
__global__ __launch_bounds__(256) void sgemm_kernel(
    const float* __restrict__ A, const float* __restrict__ W,
    const float* __restrict__ bias, float* __restrict__ C)
{
    __shared__ __align__(16) float As[8][128];
    __shared__ __align__(16) float Bs[8][128];
    const int tid = threadIdx.x;
    const int m0 = blockIdx.y * 128, n0 = blockIdx.x * 128;
    const int aRow = tid >> 1,  aCol = (tid & 1) << 2;
    const int bRow = tid >> 5,  bCol = (tid & 31) << 2;
    const int ty = tid >> 4,    tx = tid & 15;

    float acc[8][8];
    #pragma unroll
    for (int i = 0; i < 8; i++)
        #pragma unroll
        for (int j = 0; j < 8; j++) acc[i][j] = 0.f;

    for (int k0 = 0; k0 < DM; k0 += 8) {
        float4 av = *(const float4*)&A[(size_t)(m0 + aRow) * DM + k0 + aCol];
        As[aCol + 0][aRow] = av.x;
        As[aCol + 1][aRow] = av.y;
        As[aCol + 2][aRow] = av.z;
        As[aCol + 3][aRow] = av.w;

        const int n = n0 + bCol, k = k0 + bRow;
        size_t bidx = (MODE == 0) ? (size_t)k * DM + n
                                  : (size_t)(n >> 6) * (DM * DH) + (size_t)k * DH + (n & 63);
        *(float4*)&Bs[bRow][bCol] = *(const float4*)&W[bidx];
        __syncthreads();

        #pragma unroll
        for (int kk = 0; kk < 8; kk++) {
            float ra[8], rb[8];
            *(float4*)&ra[0] = *(const float4*)&As[kk][(ty << 2)];
            *(float4*)&ra[4] = *(const float4*)&As[kk][64 + (ty << 2)];
            *(float4*)&rb[0] = *(const float4*)&Bs[kk][(tx << 2)];
            *(float4*)&rb[4] = *(const float4*)&Bs[kk][64 + (tx << 2)];
            #pragma unroll
            for (int i = 0; i < 8; i++)
                #pragma unroll
                for (int j = 0; j < 8; j++)
                    acc[i][j] = fmaf(ra[i], rb[j], acc[i][j]);
        }
        __syncthreads();
    }

    #pragma unroll
    for (int i = 0; i < 8; i++) {
        const int row = m0 + (ty << 2) + (i & 3) + ((i >> 2) << 6);
        #pragma unroll
        for (int jh = 0; jh < 2; jh++) {
            const int col = n0 + (jh << 6) + (tx << 2);
            float4 bv = *(const float4*)&bias[col];
            float4 o;
            o.x = acc[i][jh * 4 + 0] + bv.x;
            o.y = acc[i][jh * 4 + 1] + bv.y;
            o.z = acc[i][jh * 4 + 2] + bv.z;
            o.w = acc[i][jh * 4 + 3] + bv.w;
            *(float4*)&C[(size_t)row * DM + col] = o;
        }
    }
}

// ---------------------------------------------------------------------------
// Flash attention, fp32. One block = one (b,h) x one 64-row q tile.
// Q/K stored transposed+swizzled in smem ([d][row], xor-swizzle on row-group
// so LDS.128 is conflict-free both when storing the transpose and reading
// outer-product fragments). K buffer is reused for P after S is computed.
// ---------------------------------------------------------------------------
__device__ __forceinline__ int swz(int d, int r) {
    return (d << 6) + ((((r >> 2) ^ (d & 15)) << 2) | (r & 3));
}

__global__ __launch_bounds__(256) void flash_kernel(
    const float* __restrict__ Q, const float* __restrict__ K,
    const float* __restrict__ V, float* __restrict__ Z)
{
    __shared__ __align__(16) float qst[64 * 64];  // Q transposed+swizzled [d][row]
    __shared__ __align__(16) float kps[64 * 64];  // K transposed+swizzled, reused as P[qrow][krow]
    __shared__ __align__(16) float vs [64 * 64];  // V natural [krow][d]

    const int tid = threadIdx.x;
    const int ty = tid >> 4, tx = tid & 15;
    const int qt = blockIdx.x;
    const int bh = blockIdx.y;
    const int b = bh >> 4, h = bh & 15;
    const size_t base = ((size_t)b * SEQ * NH + h) * DH;   // + s*1024 + d

    const int lr  = tid >> 4;          // 0..15 (4 passes of 16 rows)
    const int lc4 = (tid & 15) << 2;   // d column group

    // load Q tile (transposed + swizzled)
    #pragma unroll
    for (int p = 0; p < 4; p++) {
        const int r = lr + p * 16;
        float4 v = *(const float4*)&Q[base + (size_t)(qt * 64 + r) * DM + lc4];
        qst[swz(lc4 + 0, r)] = v.x;
        qst[swz(lc4 + 1, r)] = v.y;
        qst[swz(lc4 + 2, r)] = v.z;
        qst[swz(lc4 + 3, r)] = v.w;
    }

    float m_i[4], l_i[4], o[4][4];
    #pragma unroll
    for (int i = 0; i < 4; i++) {
        m_i[i] = -1e30f; l_i[i] = 0.f;
        #pragma unroll
        for (int j = 0; j < 4; j++) o[i][j] = 0.f;
    }

    for (int kt = 0; kt <= qt; kt++) {
        __syncthreads();   // previous-iter P/V reads complete
        #pragma unroll
        for (int p = 0; p < 4; p++) {
            const int r = lr + p * 16;
            const size_t g = base + (size_t)(kt * 64 + r) * DM + lc4;
            float4 kv = *(const float4*)&K[g];
            kps[swz(lc4 + 0, r)] = kv.x;
            kps[swz(lc4 + 1, r)] = kv.y;
            kps[swz(lc4 + 2, r)] = kv.z;
            kps[swz(lc4 + 3, r)] = kv.w;
            *(float4*)&vs[r * 64 + lc4] = *(const float4*)&V[g];
        }
        __syncthreads();

        // S = (Q K^T): outer product over d
        float s[4][4];
        #pragma unroll
        for (int i = 0; i < 4; i++)
            #pragma unroll
            for (int j = 0; j < 4; j++) s[i][j] = 0.f;

        #pragma unroll 16
        for (int d = 0; d < 64; d++) {
            float4 qf = *(const float4*)&qst[(d << 6) + ((ty ^ (d & 15)) << 2)];
            float4 kf = *(const float4*)&kps[(d << 6) + ((tx ^ (d & 15)) << 2)];
            float qa[4] = {qf.x, qf.y, qf.z, qf.w};
            float ka[4] = {kf.x, kf.y, kf.z, kf.w};
            #pragma unroll
            for (int i = 0; i < 4; i++)
                #pragma unroll
                for (int j = 0; j < 4; j++)
                    s[i][j] = fmaf(qa[i], ka[j], s[i][j]);
        }

        // scale + causal mask (only the diagonal tile needs masking)
        #pragma unroll
        for (int i = 0; i < 4; i++)
            #pragma unroll
            for (int j = 0; j < 4; j++) {
                s[i][j] *= 0.125f;
                if (kt == qt && (tx * 4 + j) > (ty * 4 + i)) s[i][j] = -1e30f;
            }

        // online softmax update
        #pragma unroll
        for (int i = 0; i < 4; i++) {
            float rm = fmaxf(fmaxf(s[i][0], s[i][1]), fmaxf(s[i][2], s[i][3]));
            #pragma unroll
            for (int off = 8; off >= 1; off >>= 1)
                rm = fmaxf(rm, __shfl_xor_sync(0xffffffffu, rm, off));
            const float mn = fmaxf(m_i[i], rm);
            float p0 = __expf(s[i][0] - mn);
            float p1 = __expf(s[i][1] - mn);
            float p2 = __expf(s[i][2] - mn);
            float p3 = __expf(s[i][3] - mn);
            float rs = p0 + p1 + p2 + p3;
            #pragma unroll
            for (int off = 8; off >= 1; off >>= 1)
                rs += __shfl_xor_sync(0xffffffffu, rs, off);
            const float alpha = __expf(m_i[i] - mn);
            l_i[i] = l_i[i] * alpha + rs;
            m_i[i] = mn;
            #pragma unroll
            for (int j = 0; j < 4; j++) o[i][j] *= alpha;
            s[i][0] = p0; s[i][1] = p1; s[i][2] = p2; s[i][3] = p3;
        }

        __syncthreads();   // all lanes done reading kps (K) before P overwrite
        #pragma unroll
        for (int i = 0; i < 4; i++) {
            float4 pv = make_float4(s[i][0], s[i][1], s[i][2], s[i][3]);
            *(float4*)&kps[(ty * 4 + i) * 64 + (tx << 2)] = pv;
        }
        __syncthreads();

        // O += P @ V
        #pragma unroll 16
        for (int j = 0; j < 64; j++) {
            float4 vf = *(const float4*)&vs[j * 64 + (tx << 2)];
            float va[4] = {vf.x, vf.y, vf.z, vf.w};
            float pj[4];
            #pragma unroll
            for (int i = 0; i < 4; i++) pj[i] = kps[(ty * 4 + i) * 64 + j];
            #pragma unroll
            for (int i = 0; i < 4; i++)
                #pragma unroll
                for (int c = 0; c < 4; c++)
                    o[i][c] = fmaf(pj[i], va[c], o[i][c]);
        }
    }

    // normalize + write z[b, s, h, d]
    #pragma unroll
    for (int i = 0; i < 4; i++) {
        const float inv = 1.f / l_i[i];
        float4 ov = make_float4(o[i][0] * inv, o[i][1] * inv, o[i][2] * inv, o[i][3] * inv);
        *(float4*)&Z[base + (size_t)(qt * 64 + ty * 4 + i) * DM + (tx << 2)] = ov;
    }
}

// ---------------------------------------------------------------------------

extern "C" void kernel_launch(void* const* d_in, const int* in_sizes, int n_in,
                              void* d_out, int out_size)
{
    const float* x  = (const float*)d_in[0];
    const float* WQ = (const float*)d_in[1];
    const float* WK = (const float*)d_in[2];
    const float* WV = (const float*)d_in[3];
    const float* WO = (const float*)d_in[4];
    const float* bQ = (const float*)d_in[5];
    const float* bK = (const float*)d_in[6];
    const float* bV = (const float*)d_in[7];
    const float* bO = (const float*)d_in[8];
    float* out = (float*)d_out;

    float *q, *k, *v, *z;
    cudaGetSymbolAddress((void**)&q, g_q);
    cudaGetSymbolAddress((void**)&k, g_k);
    cudaGetSymbolAddress((void**)&v, g_v);
    cudaGetSymbolAddress((void**)&z, g_z);

    dim3 gg(DM / 128, MTOT / 128);      // (8, 32)
    sgemm_kernel<1><<<gg, 256>>>(x, WQ, bQ, q);
    sgemm_kernel<1><<<gg, 256>>>(x, WK, bK, k);
    sgemm_kernel<1><<<gg, 256>>>(x, WV, bV, v);
    flash_kernel<<<dim3(SEQ / 64, BATCH * NH), 256>>>(q, k, v, z);
    sgemm_kernel<0><<<gg, 256>>>(z, WO, bO, out);
}

// round 3
// speedup vs baseline: 1.4242x; 1.4242x over previous
#include <cuda_runtime.h>
#include <cstdint>

#define SEQ   2048
#define BATCH 2
#define NH    16
#define DH    64
#define DM    1024
#define MTOT  (BATCH*SEQ)   // 4096 rows

// Scratch (device globals: no allocation allowed in kernel_launch)
__device__ float g_q[(size_t)MTOT * DM];
__device__ float g_k[(size_t)MTOT * DM];
__device__ float g_v[(size_t)MTOT * DM];
__device__ float g_z[(size_t)MTOT * DM];

// ===========================================================================
// mma.sync m16n8k8 tf32 (arch-portable tensor path; plain sm_100 target OK)
// ===========================================================================
__device__ __forceinline__ void mma_tf32(float* d, const unsigned* a, const unsigned* b) {
    asm volatile("mma.sync.aligned.m16n8k8.row.col.f32.tf32.tf32.f32 "
        "{%0,%1,%2,%3}, {%4,%5,%6,%7}, {%8,%9}, {%0,%1,%2,%3};"
        : "+f"(d[0]), "+f"(d[1]), "+f"(d[2]), "+f"(d[3])
        : "r"(a[0]), "r"(a[1]), "r"(a[2]), "r"(a[3]), "r"(b[0]), "r"(b[1]));
}

__device__ __forceinline__ unsigned f2tf32(float f) {
    unsigned r;
    asm("cvt.rna.tf32.f32 %0, %1;" : "=r"(r) : "f"(f));
    return r;
}

// ===========================================================================
// tf32 tensor GEMM: C[4096,1024] = A[4096,1024] @ W + bias
//   MODE 0: B[k][n] = W[k*1024 + n]                       (W_O [k][n], direct)
//   MODE 1: B[k][n] = W[(n>>6)*65536 + k*64 + (n&63)]     (W_Q/K/V [h,m,d])
// BM=128, BN=128, KC=32. 256 threads, 8 warps; warp tile 64x32.
// Smem strides: A[m][k] stride 36 floats, B[k][n] stride 132 floats
//   -> fragment reads hit bank (4*row+col)%32: conflict-free.
// ===========================================================================
#define BM 128
#define BN 128
#define KC 32
#define NCHUNK (DM / KC)   // 32
#define AST 36             // A smem row stride (floats)
#define BST 132            // B smem row stride (floats)

template<int MODE>
__global__ __launch_bounds__(256) void tc_gemm(
    const float* __restrict__ A, const float* __restrict__ W,
    const float* __restrict__ bias, float* __restrict__ C)
{
    __shared__ __align__(16) unsigned As[BM * AST];   // 18432 B
    __shared__ __align__(16) unsigned Bs[KC * BST];   // 16896 B

    const int tid = threadIdx.x;
    const int wid = tid >> 5, lane = tid & 31;
    const int g = lane >> 2, tig = lane & 3;
    const int warp_m = wid & 1, warp_n = wid >> 1;    // 2 x 4 warp grid
    const int m0 = blockIdx.y * BM, n0 = blockIdx.x * BN;

    // --- load geometry ---
    // A: thread covers row ra = tid>>1, 16 k-values at ka..ka+15
    const int ra = tid >> 1;
    const int ka = (tid & 1) * 16;
    const float* Aptr = A + (size_t)(m0 + ra) * DM + ka;
    // B: thread covers 4 consecutive n at nb (float4), 4 k-values kb..kb+3
    const int nb = (lane) * 4;           // n offset within tile (lane*4: 0..124)
    const int kb = wid * 4;              // k offset within chunk (wid*4: 0..28)
    const int n_g = n0 + nb;
    const float* Bptr = (MODE == 1)
        ? W + (size_t)(n_g >> 6) * (DM * DH) + (n_g & 63)
        : W + n_g;
    const size_t bstride = (MODE == 1) ? DH : DM;     // floats per +1 k

    float acc[4][4][4];
    #pragma unroll
    for (int mt = 0; mt < 4; mt++)
        #pragma unroll
        for (int nt = 0; nt < 4; nt++)
            #pragma unroll
            for (int i = 0; i < 4; i++) acc[mt][nt][i] = 0.f;

    float4 pa[4], pb[4];
    #pragma unroll
    for (int f = 0; f < 4; f++) pa[f] = *(const float4*)(Aptr + f * 4);
    #pragma unroll
    for (int j = 0; j < 4; j++) pb[j] = *(const float4*)(Bptr + (size_t)(kb + j) * bstride);

    for (int c = 0; c < NCHUNK; c++) {
        // STS chunk c (convert fp32 -> tf32 rna at store time)
        #pragma unroll
        for (int f = 0; f < 4; f++) {
            uint4 u = { f2tf32(pa[f].x), f2tf32(pa[f].y), f2tf32(pa[f].z), f2tf32(pa[f].w) };
            *(uint4*)&As[ra * AST + ka + 4 * f] = u;
        }
        #pragma unroll
        for (int j = 0; j < 4; j++) {
            uint4 u = { f2tf32(pb[j].x), f2tf32(pb[j].y), f2tf32(pb[j].z), f2tf32(pb[j].w) };
            *(uint4*)&Bs[(kb + j) * BST + nb] = u;
        }
        __syncthreads();

        // prefetch chunk c+1 (LDG latency overlaps mma below)
        if (c + 1 < NCHUNK) {
            const int k0g = (c + 1) * KC;
            #pragma unroll
            for (int f = 0; f < 4; f++) pa[f] = *(const float4*)(Aptr + k0g + f * 4);
            #pragma unroll
            for (int j = 0; j < 4; j++)
                pb[j] = *(const float4*)(Bptr + (size_t)(k0g + kb + j) * bstride);
        }

        // compute: 4 k-steps of 8
        #pragma unroll
        for (int kk = 0; kk < 4; kk++) {
            const int k0 = kk * 8;
            unsigned af[4][4], bf[4][2];
            #pragma unroll
            for (int mt = 0; mt < 4; mt++) {
                const int rb = warp_m * 64 + mt * 16 + g;
                af[mt][0] = As[rb * AST + k0 + tig];
                af[mt][1] = As[(rb + 8) * AST + k0 + tig];
                af[mt][2] = As[rb * AST + k0 + tig + 4];
                af[mt][3] = As[(rb + 8) * AST + k0 + tig + 4];
            }
            #pragma unroll
            for (int nt = 0; nt < 4; nt++) {
                const int cb = warp_n * 32 + nt * 8 + g;
                bf[nt][0] = Bs[(k0 + tig) * BST + cb];
                bf[nt][1] = Bs[(k0 + tig + 4) * BST + cb];
            }
            #pragma unroll
            for (int mt = 0; mt < 4; mt++)
                #pragma unroll
                for (int nt = 0; nt < 4; nt++)
                    mma_tf32(acc[mt][nt], af[mt], bf[nt]);
        }
        __syncthreads();
    }

    // epilogue: C fragment c0/c1 at (row=g, col=2*tig, 2*tig+1), c2/c3 at row g+8
    #pragma unroll
    for (int mt = 0; mt < 4; mt++) {
        const int r0 = m0 + warp_m * 64 + mt * 16 + g;
        #pragma unroll
        for (int nt = 0; nt < 4; nt++) {
            const int col = n0 + warp_n * 32 + nt * 8 + 2 * tig;
            const float bx = bias[col], by = bias[col + 1];
            float2 v0 = { acc[mt][nt][0] + bx, acc[mt][nt][1] + by };
            float2 v1 = { acc[mt][nt][2] + bx, acc[mt][nt][3] + by };
            *(float2*)&C[(size_t)r0 * DM + col] = v0;
            *(float2*)&C[(size_t)(r0 + 8) * DM + col] = v1;
        }
    }
}

// ---------------------------------------------------------------------------
// Flash attention, fp32 SIMT (unchanged from R1)
// ---------------------------------------------------------------------------
__device__ __forceinline__ int swz(int d, int r) {
    return (d << 6) + ((((r >> 2) ^ (d & 15)) << 2) | (r & 3));
}

__global__ __launch_bounds__(256) void flash_kernel(
    const float* __restrict__ Q, const float* __restrict__ K,
    const float* __restrict__ V, float* __restrict__ Z)
{
    __shared__ __align__(16) float qst[64 * 64];
    __shared__ __align__(16) float kps[64 * 64];
    __shared__ __align__(16) float vs [64 * 64];

    const int tid = threadIdx.x;
    const int ty = tid >> 4, tx = tid & 15;
    const int qt = blockIdx.x;
    const int bh = blockIdx.y;
    const int b = bh >> 4, h = bh & 15;
    const size_t base = ((size_t)b * SEQ * NH + h) * DH;

    const int lr  = tid >> 4;
    const int lc4 = (tid & 15) << 2;

    #pragma unroll
    for (int p = 0; p < 4; p++) {
        const int r = lr + p * 16;
        float4 v = *(const float4*)&Q[base + (size_t)(qt * 64 + r) * DM + lc4];
        qst[swz(lc4 + 0, r)] = v.x;
        qst[swz(lc4 + 1, r)] = v.y;
        qst[swz(lc4 + 2, r)] = v.z;
        qst[swz(lc4 + 3, r)] = v.w;
    }

    float m_i[4], l_i[4], o[4][4];
    #pragma unroll
    for (int i = 0; i < 4; i++) {
        m_i[i] = -1e30f; l_i[i] = 0.f;
        #pragma unroll
        for (int j = 0; j < 4; j++) o[i][j] = 0.f;
    }

    for (int kt = 0; kt <= qt; kt++) {
        __syncthreads();
        #pragma unroll
        for (int p = 0; p < 4; p++) {
            const int r = lr + p * 16;
            const size_t gidx = base + (size_t)(kt * 64 + r) * DM + lc4;
            float4 kv = *(const float4*)&K[gidx];
            kps[swz(lc4 + 0, r)] = kv.x;
            kps[swz(lc4 + 1, r)] = kv.y;
            kps[swz(lc4 + 2, r)] = kv.z;
            kps[swz(lc4 + 3, r)] = kv.w;
            *(float4*)&vs[r * 64 + lc4] = *(const float4*)&V[gidx];
        }
        __syncthreads();

        float s[4][4];
        #pragma unroll
        for (int i = 0; i < 4; i++)
            #pragma unroll
            for (int j = 0; j < 4; j++) s[i][j] = 0.f;

        #pragma unroll 16
        for (int d = 0; d < 64; d++) {
            float4 qf = *(const float4*)&qst[(d << 6) + ((ty ^ (d & 15)) << 2)];
            float4 kf = *(const float4*)&kps[(d << 6) + ((tx ^ (d & 15)) << 2)];
            float qa[4] = {qf.x, qf.y, qf.z, qf.w};
            float ka[4] = {kf.x, kf.y, kf.z, kf.w};
            #pragma unroll
            for (int i = 0; i < 4; i++)
                #pragma unroll
                for (int j = 0; j < 4; j++)
                    s[i][j] = fmaf(qa[i], ka[j], s[i][j]);
        }

        #pragma unroll
        for (int i = 0; i < 4; i++)
            #pragma unroll
            for (int j = 0; j < 4; j++) {
                s[i][j] *= 0.125f;
                if (kt == qt && (tx * 4 + j) > (ty * 4 + i)) s[i][j] = -1e30f;
            }

        #pragma unroll
        for (int i = 0; i < 4; i++) {
            float rm = fmaxf(fmaxf(s[i][0], s[i][1]), fmaxf(s[i][2], s[i][3]));
            #pragma unroll
            for (int off = 8; off >= 1; off >>= 1)
                rm = fmaxf(rm, __shfl_xor_sync(0xffffffffu, rm, off));
            const float mn = fmaxf(m_i[i], rm);
            float p0 = __expf(s[i][0] - mn);
            float p1 = __expf(s[i][1] - mn);
            float p2 = __expf(s[i][2] - mn);
            float p3 = __expf(s[i][3] - mn);
            float rs = p0 + p1 + p2 + p3;
            #pragma unroll
            for (int off = 8; off >= 1; off >>= 1)
                rs += __shfl_xor_sync(0xffffffffu, rs, off);
            const float alpha = __expf(m_i[i] - mn);
            l_i[i] = l_i[i] * alpha + rs;
            m_i[i] = mn;
            #pragma unroll
            for (int j = 0; j < 4; j++) o[i][j] *= alpha;
            s[i][0] = p0; s[i][1] = p1; s[i][2] = p2; s[i][3] = p3;
        }

        __syncthreads();
        #pragma unroll
        for (int i = 0; i < 4; i++) {
            float4 pv = make_float4(s[i][0], s[i][1], s[i][2], s[i][3]);
            *(float4*)&kps[(ty * 4 + i) * 64 + (tx << 2)] = pv;
        }
        __syncthreads();

        #pragma unroll 16
        for (int j = 0; j < 64; j++) {
            float4 vf = *(const float4*)&vs[j * 64 + (tx << 2)];
            float va[4] = {vf.x, vf.y, vf.z, vf.w};
            float pj[4];
            #pragma unroll
            for (int i = 0; i < 4; i++) pj[i] = kps[(ty * 4 + i) * 64 + j];
            #pragma unroll
            for (int i = 0; i < 4; i++)
                #pragma unroll
                for (int cc = 0; cc < 4; cc++)
                    o[i][cc] = fmaf(pj[i], va[cc], o[i][cc]);
        }
    }

    #pragma unroll
    for (int i = 0; i < 4; i++) {
        const float inv = 1.f / l_i[i];
        float4 ov = make_float4(o[i][0] * inv, o[i][1] * inv, o[i][2] * inv, o[i][3] * inv);
        *(float4*)&Z[base + (size_t)(qt * 64 + ty * 4 + i) * DM + (tx << 2)] = ov;
    }
}

// ---------------------------------------------------------------------------

extern "C" void kernel_launch(void* const* d_in, const int* in_sizes, int n_in,
                              void* d_out, int out_size)
{
    const float* x  = (const float*)d_in[0];
    const float* WQ = (const float*)d_in[1];
    const float* WK = (const float*)d_in[2];
    const float* WV = (const float*)d_in[3];
    const float* WO = (const float*)d_in[4];
    const float* bQ = (const float*)d_in[5];
    const float* bK = (const float*)d_in[6];
    const float* bV = (const float*)d_in[7];
    const float* bO = (const float*)d_in[8];
    float* out = (float*)d_out;

    float *q, *k, *v, *z;
    cudaGetSymbolAddress((void**)&q, g_q);
    cudaGetSymbolAddress((void**)&k, g_k);
    cudaGetSymbolAddress((void**)&v, g_v);
    cudaGetSymbolAddress((void**)&z, g_z);

    dim3 gg(DM / BN, MTOT / BM);        // (8, 32)
    tc_gemm<1><<<gg, 256>>>(x, WQ, bQ, q);
    tc_gemm<1><<<gg, 256>>>(x, WK, bK, k);
    tc_gemm<1><<<gg, 256>>>(x, WV, bV, v);
    flash_kernel<<<dim3(SEQ / 64, BATCH * NH), 256>>>(q, k, v, z);
    tc_gemm<0><<<gg, 256>>>(z, WO, bO, out);
}

// round 4
// speedup vs baseline: 2.3210x; 1.6297x over previous
#include <cuda_runtime.h>
#include <cstdint>

#define SEQ   2048
#define BATCH 2
#define NH    16
#define DH    64
#define DM    1024
#define MTOT  (BATCH*SEQ)   // 4096 rows

// Scratch (device globals: no allocation allowed in kernel_launch)
__device__ float g_q[(size_t)MTOT * DM];
__device__ float g_k[(size_t)MTOT * DM];
__device__ float g_v[(size_t)MTOT * DM];
__device__ float g_z[(size_t)MTOT * DM];

// ===========================================================================
// mma.sync m16n8k8 tf32 (arch-portable tensor path)
// ===========================================================================
__device__ __forceinline__ void mma_tf32(float* d, const unsigned* a, const unsigned* b) {
    asm volatile("mma.sync.aligned.m16n8k8.row.col.f32.tf32.tf32.f32 "
        "{%0,%1,%2,%3}, {%4,%5,%6,%7}, {%8,%9}, {%0,%1,%2,%3};"
        : "+f"(d[0]), "+f"(d[1]), "+f"(d[2]), "+f"(d[3])
        : "r"(a[0]), "r"(a[1]), "r"(a[2]), "r"(a[3]), "r"(b[0]), "r"(b[1]));
}

__device__ __forceinline__ unsigned f2tf32(float f) {
    unsigned r;
    asm("cvt.rna.tf32.f32 %0, %1;" : "=r"(r) : "f"(f));
    return r;
}

// ===========================================================================
// tf32 tensor GEMM (unchanged from R3): C[4096,1024] = A @ W + bias
// ===========================================================================
#define BM 128
#define BN 128
#define KC 32
#define NCHUNK (DM / KC)   // 32
#define AST 36
#define BST 132

template<int MODE>
__global__ __launch_bounds__(256) void tc_gemm(
    const float* __restrict__ A, const float* __restrict__ W,
    const float* __restrict__ bias, float* __restrict__ C)
{
    __shared__ __align__(16) unsigned As[BM * AST];
    __shared__ __align__(16) unsigned Bs[KC * BST];

    const int tid = threadIdx.x;
    const int wid = tid >> 5, lane = tid & 31;
    const int g = lane >> 2, tig = lane & 3;
    const int warp_m = wid & 1, warp_n = wid >> 1;
    const int m0 = blockIdx.y * BM, n0 = blockIdx.x * BN;

    const int ra = tid >> 1;
    const int ka = (tid & 1) * 16;
    const float* Aptr = A + (size_t)(m0 + ra) * DM + ka;
    const int nb = lane * 4;
    const int kb = wid * 4;
    const int n_g = n0 + nb;
    const float* Bptr = (MODE == 1)
        ? W + (size_t)(n_g >> 6) * (DM * DH) + (n_g & 63)
        : W + n_g;
    const size_t bstride = (MODE == 1) ? DH : DM;

    float acc[4][4][4];
    #pragma unroll
    for (int mt = 0; mt < 4; mt++)
        #pragma unroll
        for (int nt = 0; nt < 4; nt++)
            #pragma unroll
            for (int i = 0; i < 4; i++) acc[mt][nt][i] = 0.f;

    float4 pa[4], pb[4];
    #pragma unroll
    for (int f = 0; f < 4; f++) pa[f] = *(const float4*)(Aptr + f * 4);
    #pragma unroll
    for (int j = 0; j < 4; j++) pb[j] = *(const float4*)(Bptr + (size_t)(kb + j) * bstride);

    for (int c = 0; c < NCHUNK; c++) {
        #pragma unroll
        for (int f = 0; f < 4; f++) {
            uint4 u = { f2tf32(pa[f].x), f2tf32(pa[f].y), f2tf32(pa[f].z), f2tf32(pa[f].w) };
            *(uint4*)&As[ra * AST + ka + 4 * f] = u;
        }
        #pragma unroll
        for (int j = 0; j < 4; j++) {
            uint4 u = { f2tf32(pb[j].x), f2tf32(pb[j].y), f2tf32(pb[j].z), f2tf32(pb[j].w) };
            *(uint4*)&Bs[(kb + j) * BST + nb] = u;
        }
        __syncthreads();

        if (c + 1 < NCHUNK) {
            const int k0g = (c + 1) * KC;
            #pragma unroll
            for (int f = 0; f < 4; f++) pa[f] = *(const float4*)(Aptr + k0g + f * 4);
            #pragma unroll
            for (int j = 0; j < 4; j++)
                pb[j] = *(const float4*)(Bptr + (size_t)(k0g + kb + j) * bstride);
        }

        #pragma unroll
        for (int kk = 0; kk < 4; kk++) {
            const int k0 = kk * 8;
            unsigned af[4][4], bf[4][2];
            #pragma unroll
            for (int mt = 0; mt < 4; mt++) {
                const int rb = warp_m * 64 + mt * 16 + g;
                af[mt][0] = As[rb * AST + k0 + tig];
                af[mt][1] = As[(rb + 8) * AST + k0 + tig];
                af[mt][2] = As[rb * AST + k0 + tig + 4];
                af[mt][3] = As[(rb + 8) * AST + k0 + tig + 4];
            }
            #pragma unroll
            for (int nt = 0; nt < 4; nt++) {
                const int cb = warp_n * 32 + nt * 8 + g;
                bf[nt][0] = Bs[(k0 + tig) * BST + cb];
                bf[nt][1] = Bs[(k0 + tig + 4) * BST + cb];
            }
            #pragma unroll
            for (int mt = 0; mt < 4; mt++)
                #pragma unroll
                for (int nt = 0; nt < 4; nt++)
                    mma_tf32(acc[mt][nt], af[mt], bf[nt]);
        }
        __syncthreads();
    }

    #pragma unroll
    for (int mt = 0; mt < 4; mt++) {
        const int r0 = m0 + warp_m * 64 + mt * 16 + g;
        #pragma unroll
        for (int nt = 0; nt < 4; nt++) {
            const int col = n0 + warp_n * 32 + nt * 8 + 2 * tig;
            const float bx = bias[col], by = bias[col + 1];
            float2 v0 = { acc[mt][nt][0] + bx, acc[mt][nt][1] + by };
            float2 v1 = { acc[mt][nt][2] + bx, acc[mt][nt][3] + by };
            *(float2*)&C[(size_t)r0 * DM + col] = v0;
            *(float2*)&C[(size_t)(r0 + 8) * DM + col] = v1;
        }
    }
}

// ===========================================================================
// Flash attention with mma.sync tf32.
// Block = 128 q rows x one (b,h). 8 warps, 16 q rows each. kv tiles of 64.
// Q in register A-fragments (scale 1/8 folded). K smem [kv][d] str 68,
// V smem transposed [d][kv] str 68 -> B-frag LDS banks 4g+tig, conflict-free.
// P stays in registers: S-accum fragment -> A fragment via 8 shfl per k-step.
// ===========================================================================
#define KST 68   // smem row stride (floats) for K/V tiles

__global__ __launch_bounds__(256) void flash_mma(
    const float* __restrict__ Q, const float* __restrict__ K,
    const float* __restrict__ V, float* __restrict__ Z)
{
    __shared__ __align__(16) unsigned ks[64 * KST];
    __shared__ __align__(16) unsigned vs[64 * KST];

    const int tid = threadIdx.x;
    const int wid = tid >> 5, lane = tid & 31;
    const int g = lane >> 2, tig = lane & 3;
    const int qt = gridDim.x - 1 - blockIdx.x;       // heavy tiles first
    const int bh = blockIdx.y;
    const int b = bh >> 4, h = bh & 15;
    const size_t base = ((size_t)b * SEQ * NH + h) * DH;
    const int qrow0 = qt * 128 + wid * 16;

    const int lkv = tid >> 2;          // staging row 0..63
    const int ld0 = (tid & 3) * 16;    // staging col group

    // ---- Q -> register A-fragments (two passes through ks) ----
    unsigned aq[8][4];
    #pragma unroll
    for (int pass = 0; pass < 2; pass++) {
        const int srow = qt * 128 + pass * 64 + lkv;
        #pragma unroll
        for (int i = 0; i < 4; i++) {
            float4 qv = *(const float4*)&Q[base + (size_t)srow * DM + ld0 + 4 * i];
            uint4 u = { f2tf32(qv.x * 0.125f), f2tf32(qv.y * 0.125f),
                        f2tf32(qv.z * 0.125f), f2tf32(qv.w * 0.125f) };
            *(uint4*)&ks[lkv * KST + ld0 + 4 * i] = u;
        }
        __syncthreads();
        if ((wid >> 2) == pass) {
            const int r = (wid & 3) * 16 + g;
            #pragma unroll
            for (int kk = 0; kk < 8; kk++) {
                aq[kk][0] = ks[r * KST + kk * 8 + tig];
                aq[kk][1] = ks[(r + 8) * KST + kk * 8 + tig];
                aq[kk][2] = ks[r * KST + kk * 8 + tig + 4];
                aq[kk][3] = ks[(r + 8) * KST + kk * 8 + tig + 4];
            }
        }
        __syncthreads();
    }

    float m0 = -1e30f, m1 = -1e30f, l0 = 0.f, l1 = 0.f;
    float oacc[8][4];
    #pragma unroll
    for (int nt = 0; nt < 8; nt++)
        #pragma unroll
        for (int i = 0; i < 4; i++) oacc[nt][i] = 0.f;

    const int vkv = tid & 63;          // V staging: column-load for transpose
    const int vd0 = (tid >> 6) * 16;
    const unsigned s1 = (lane & 28) | (tig >> 1);
    const unsigned s2 = s1 + 2;
    const int NKT = 2 * qt + 2;

    for (int kt = 0; kt < NKT; kt++) {
        const int ktb = kt * 64;
        __syncthreads();
        // K tile [kv][d]
        #pragma unroll
        for (int i = 0; i < 4; i++) {
            float4 kv4 = *(const float4*)&K[base + (size_t)(ktb + lkv) * DM + ld0 + 4 * i];
            uint4 u = { f2tf32(kv4.x), f2tf32(kv4.y), f2tf32(kv4.z), f2tf32(kv4.w) };
            *(uint4*)&ks[lkv * KST + ld0 + 4 * i] = u;
        }
        // V tile transposed -> [d][kv]
        #pragma unroll
        for (int i = 0; i < 4; i++) {
            float4 vv = *(const float4*)&V[base + (size_t)(ktb + vkv) * DM + vd0 + 4 * i];
            vs[(vd0 + 4 * i + 0) * KST + vkv] = f2tf32(vv.x);
            vs[(vd0 + 4 * i + 1) * KST + vkv] = f2tf32(vv.y);
            vs[(vd0 + 4 * i + 2) * KST + vkv] = f2tf32(vv.z);
            vs[(vd0 + 4 * i + 3) * KST + vkv] = f2tf32(vv.w);
        }
        __syncthreads();

        if (ktb > qrow0 + 15) continue;   // tile fully masked for this warp

        // ---- S = Q K^T ----
        float sacc[8][4];
        #pragma unroll
        for (int nt = 0; nt < 8; nt++)
            #pragma unroll
            for (int i = 0; i < 4; i++) sacc[nt][i] = 0.f;

        #pragma unroll
        for (int kk = 0; kk < 8; kk++) {
            unsigned bf[8][2];
            #pragma unroll
            for (int nt = 0; nt < 8; nt++) {
                bf[nt][0] = ks[(nt * 8 + g) * KST + kk * 8 + tig];
                bf[nt][1] = ks[(nt * 8 + g) * KST + kk * 8 + tig + 4];
            }
            #pragma unroll
            for (int nt = 0; nt < 8; nt++)
                mma_tf32(sacc[nt], aq[kk], bf[nt]);
        }

        // ---- causal mask (diagonal tiles only) ----
        if (ktb + 63 > qrow0) {
            #pragma unroll
            for (int nt = 0; nt < 8; nt++) {
                const int kv0 = ktb + nt * 8 + 2 * tig;
                if (kv0     > qrow0 + g)     sacc[nt][0] = -1e30f;
                if (kv0 + 1 > qrow0 + g)     sacc[nt][1] = -1e30f;
                if (kv0     > qrow0 + g + 8) sacc[nt][2] = -1e30f;
                if (kv0 + 1 > qrow0 + g + 8) sacc[nt][3] = -1e30f;
            }
        }

        // ---- online softmax ----
        float rm0 = -1e30f, rm1 = -1e30f;
        #pragma unroll
        for (int nt = 0; nt < 8; nt++) {
            rm0 = fmaxf(rm0, fmaxf(sacc[nt][0], sacc[nt][1]));
            rm1 = fmaxf(rm1, fmaxf(sacc[nt][2], sacc[nt][3]));
        }
        rm0 = fmaxf(rm0, __shfl_xor_sync(0xffffffffu, rm0, 1));
        rm0 = fmaxf(rm0, __shfl_xor_sync(0xffffffffu, rm0, 2));
        rm1 = fmaxf(rm1, __shfl_xor_sync(0xffffffffu, rm1, 1));
        rm1 = fmaxf(rm1, __shfl_xor_sync(0xffffffffu, rm1, 2));
        const float mn0 = fmaxf(m0, rm0), mn1 = fmaxf(m1, rm1);
        const float al0 = __expf(m0 - mn0), al1 = __expf(m1 - mn1);
        float rs0 = 0.f, rs1 = 0.f;
        #pragma unroll
        for (int nt = 0; nt < 8; nt++) {
            sacc[nt][0] = __expf(sacc[nt][0] - mn0); rs0 += sacc[nt][0];
            sacc[nt][1] = __expf(sacc[nt][1] - mn0); rs0 += sacc[nt][1];
            sacc[nt][2] = __expf(sacc[nt][2] - mn1); rs1 += sacc[nt][2];
            sacc[nt][3] = __expf(sacc[nt][3] - mn1); rs1 += sacc[nt][3];
        }
        rs0 += __shfl_xor_sync(0xffffffffu, rs0, 1);
        rs0 += __shfl_xor_sync(0xffffffffu, rs0, 2);
        rs1 += __shfl_xor_sync(0xffffffffu, rs1, 1);
        rs1 += __shfl_xor_sync(0xffffffffu, rs1, 2);
        l0 = l0 * al0 + rs0;  l1 = l1 * al1 + rs1;
        m0 = mn0;             m1 = mn1;
        #pragma unroll
        for (int nt = 0; nt < 8; nt++) {
            oacc[nt][0] *= al0; oacc[nt][1] *= al0;
            oacc[nt][2] *= al1; oacc[nt][3] *= al1;
        }

        // ---- O += P V  (P fragment via shfl from S fragment) ----
        #pragma unroll
        for (int kk = 0; kk < 8; kk++) {
            const float c0a = __shfl_sync(0xffffffffu, sacc[kk][0], s1);
            const float c1a = __shfl_sync(0xffffffffu, sacc[kk][1], s1);
            const float c2a = __shfl_sync(0xffffffffu, sacc[kk][2], s1);
            const float c3a = __shfl_sync(0xffffffffu, sacc[kk][3], s1);
            const float c0b = __shfl_sync(0xffffffffu, sacc[kk][0], s2);
            const float c1b = __shfl_sync(0xffffffffu, sacc[kk][1], s2);
            const float c2b = __shfl_sync(0xffffffffu, sacc[kk][2], s2);
            const float c3b = __shfl_sync(0xffffffffu, sacc[kk][3], s2);
            unsigned ap[4];
            ap[0] = f2tf32((tig & 1) ? c1a : c0a);
            ap[1] = f2tf32((tig & 1) ? c3a : c2a);
            ap[2] = f2tf32((tig & 1) ? c1b : c0b);
            ap[3] = f2tf32((tig & 1) ? c3b : c2b);
            unsigned bf[8][2];
            #pragma unroll
            for (int nt = 0; nt < 8; nt++) {
                bf[nt][0] = vs[(nt * 8 + g) * KST + kk * 8 + tig];
                bf[nt][1] = vs[(nt * 8 + g) * KST + kk * 8 + tig + 4];
            }
            #pragma unroll
            for (int nt = 0; nt < 8; nt++)
                mma_tf32(oacc[nt], ap, bf[nt]);
        }
    }

    // ---- normalize + write z[b, s, h, d] ----
    const float i0 = 1.f / l0, i1 = 1.f / l1;
    #pragma unroll
    for (int nt = 0; nt < 8; nt++) {
        const int col = nt * 8 + 2 * tig;
        const int row = qrow0 + g;
        float2 v0 = { oacc[nt][0] * i0, oacc[nt][1] * i0 };
        float2 v1 = { oacc[nt][2] * i1, oacc[nt][3] * i1 };
        *(float2*)&Z[base + (size_t)row * DM + col] = v0;
        *(float2*)&Z[base + (size_t)(row + 8) * DM + col] = v1;
    }
}

// ---------------------------------------------------------------------------

extern "C" void kernel_launch(void* const* d_in, const int* in_sizes, int n_in,
                              void* d_out, int out_size)
{
    const float* x  = (const float*)d_in[0];
    const float* WQ = (const float*)d_in[1];
    const float* WK = (const float*)d_in[2];
    const float* WV = (const float*)d_in[3];
    const float* WO = (const float*)d_in[4];
    const float* bQ = (const float*)d_in[5];
    const float* bK = (const float*)d_in[6];
    const float* bV = (const float*)d_in[7];
    const float* bO = (const float*)d_in[8];
    float* out = (float*)d_out;

    float *q, *k, *v, *z;
    cudaGetSymbolAddress((void**)&q, g_q);
    cudaGetSymbolAddress((void**)&k, g_k);
    cudaGetSymbolAddress((void**)&v, g_v);
    cudaGetSymbolAddress((void**)&z, g_z);

    dim3 gg(DM / BN, MTOT / BM);        // (8, 32)
    tc_gemm<1><<<gg, 256>>>(x, WQ, bQ, q);
    tc_gemm<1><<<gg, 256>>>(x, WK, bK, k);
    tc_gemm<1><<<gg, 256>>>(x, WV, bV, v);
    flash_mma<<<dim3(SEQ / 128, BATCH * NH), 256>>>(q, k, v, z);
    tc_gemm<0><<<gg, 256>>>(z, WO, bO, out);
}

// round 5
// speedup vs baseline: 2.3678x; 1.0202x over previous
#include <cuda_runtime.h>
#include <cstdint>

#define SEQ   2048
#define BATCH 2
#define NH    16
#define DH    64
#define DM    1024
#define MTOT  (BATCH*SEQ)   // 4096 rows

// Scratch (device globals: no allocation allowed in kernel_launch)
__device__ float g_q[(size_t)MTOT * DM];
__device__ float g_k[(size_t)MTOT * DM];
__device__ float g_v[(size_t)MTOT * DM];
__device__ float g_z[(size_t)MTOT * DM];

// ===========================================================================
// mma.sync m16n8k8 tf32 + cp.async helpers
// ===========================================================================
__device__ __forceinline__ void mma_tf32(float* d, const unsigned* a, const unsigned* b) {
    asm volatile("mma.sync.aligned.m16n8k8.row.col.f32.tf32.tf32.f32 "
        "{%0,%1,%2,%3}, {%4,%5,%6,%7}, {%8,%9}, {%0,%1,%2,%3};"
        : "+f"(d[0]), "+f"(d[1]), "+f"(d[2]), "+f"(d[3])
        : "r"(a[0]), "r"(a[1]), "r"(a[2]), "r"(a[3]), "r"(b[0]), "r"(b[1]));
}

__device__ __forceinline__ unsigned f2tf32(float f) {
    unsigned r;
    asm("cvt.rna.tf32.f32 %0, %1;" : "=r"(r) : "f"(f));
    return r;
}

__device__ __forceinline__ unsigned smem_u32(const void* p) {
    unsigned r;
    asm("{ .reg .u64 t; cvta.to.shared.u64 t, %1; cvt.u32.u64 %0, t; }"
        : "=r"(r) : "l"(p));
    return r;
}

__device__ __forceinline__ void cp16(unsigned dst, const void* src) {
    asm volatile("cp.async.cg.shared.global [%0], [%1], 16;" :: "r"(dst), "l"(src));
}
#define CP_COMMIT()  asm volatile("cp.async.commit_group;" ::: "memory")
#define CP_WAIT(n)   asm volatile("cp.async.wait_group %0;" :: "n"(n) : "memory")

// ===========================================================================
// tf32 tensor GEMM, cp.async 2-stage pipeline:
//   C[4096,1024] = A[4096,1024] @ W + bias
//   MODE 0: B[k][n] = W[k*1024 + n]       MODE 1: W[(n>>6)*65536 + k*64 + (n&63)]
// Smem (floats): As[2] @ 0 / 4608 (128x36), Bs[2] @ 9216 / 13440 (32x132).
// Total 17664 floats = 70656 B dynamic.
// ===========================================================================
#define BM 128
#define BN 128
#define KC 32
#define NCHUNK (DM / KC)   // 32
#define AST 36
#define BST 132
#define GEMM_SMEM 70656

template<int MODE>
__global__ __launch_bounds__(256, 2) void tc_gemm(
    const float* __restrict__ A, const float* __restrict__ W,
    const float* __restrict__ bias, float* __restrict__ C)
{
    extern __shared__ __align__(16) float smemf[];
    const unsigned sbase = smem_u32(smemf);

    const int tid = threadIdx.x;
    const int wid = tid >> 5, lane = tid & 31;
    const int g = lane >> 2, tig = lane & 3;
    const int warp_m = wid & 1, warp_n = wid >> 1;
    const int m0 = blockIdx.y * BM, n0 = blockIdx.x * BN;

    // load geometry
    const int ra = tid >> 1, ka = (tid & 1) * 16;
    const float* Aptr = A + (size_t)(m0 + ra) * DM + ka;
    const unsigned aDst = sbase + (ra * AST + ka) * 4;
    const int nb = lane * 4, kb = wid * 4;
    const int n_g = n0 + nb;
    const float* Bptr = (MODE == 1)
        ? W + (size_t)(n_g >> 6) * (DM * DH) + (n_g & 63)
        : W + n_g;
    const size_t bstride = (MODE == 1) ? DH : DM;
    const unsigned bDst = sbase + (9216 + kb * BST + nb) * 4;

    float acc[4][4][4];
    #pragma unroll
    for (int mt = 0; mt < 4; mt++)
        #pragma unroll
        for (int nt = 0; nt < 4; nt++)
            #pragma unroll
            for (int i = 0; i < 4; i++) acc[mt][nt][i] = 0.f;

    // stage chunk c into buffer buf
    auto stage = [&](int c, int buf) {
        const float* ap = Aptr + c * KC;
        const unsigned ad = aDst + buf * (4608 * 4);
        #pragma unroll
        for (int f = 0; f < 4; f++) cp16(ad + f * 16, ap + f * 4);
        const unsigned bd = bDst + buf * (4224 * 4);
        #pragma unroll
        for (int j = 0; j < 4; j++)
            cp16(bd + j * (BST * 4), Bptr + (size_t)(c * KC + kb + j) * bstride);
    };

    stage(0, 0); CP_COMMIT();

    for (int c = 0; c < NCHUNK; c++) {
        if (c + 1 < NCHUNK) { stage(c + 1, (c + 1) & 1); CP_COMMIT(); CP_WAIT(1); }
        else                { CP_WAIT(0); }
        __syncthreads();

        const float* Asb = smemf + (c & 1) * 4608;
        const float* Bsb = smemf + 9216 + (c & 1) * 4224;
        #pragma unroll
        for (int kk = 0; kk < 4; kk++) {
            const int k0 = kk * 8;
            unsigned af[4][4], bf[4][2];
            #pragma unroll
            for (int mt = 0; mt < 4; mt++) {
                const int rb = warp_m * 64 + mt * 16 + g;
                af[mt][0] = f2tf32(Asb[rb * AST + k0 + tig]);
                af[mt][1] = f2tf32(Asb[(rb + 8) * AST + k0 + tig]);
                af[mt][2] = f2tf32(Asb[rb * AST + k0 + tig + 4]);
                af[mt][3] = f2tf32(Asb[(rb + 8) * AST + k0 + tig + 4]);
            }
            #pragma unroll
            for (int nt = 0; nt < 4; nt++) {
                const int cb = warp_n * 32 + nt * 8 + g;
                bf[nt][0] = f2tf32(Bsb[(k0 + tig) * BST + cb]);
                bf[nt][1] = f2tf32(Bsb[(k0 + tig + 4) * BST + cb]);
            }
            #pragma unroll
            for (int mt = 0; mt < 4; mt++)
                #pragma unroll
                for (int nt = 0; nt < 4; nt++)
                    mma_tf32(acc[mt][nt], af[mt], bf[nt]);
        }
        __syncthreads();
    }

    #pragma unroll
    for (int mt = 0; mt < 4; mt++) {
        const int r0 = m0 + warp_m * 64 + mt * 16 + g;
        #pragma unroll
        for (int nt = 0; nt < 4; nt++) {
            const int col = n0 + warp_n * 32 + nt * 8 + 2 * tig;
            const float bx = bias[col], by = bias[col + 1];
            float2 v0 = { acc[mt][nt][0] + bx, acc[mt][nt][1] + by };
            float2 v1 = { acc[mt][nt][2] + bx, acc[mt][nt][3] + by };
            *(float2*)&C[(size_t)r0 * DM + col] = v0;
            *(float2*)&C[(size_t)(r0 + 8) * DM + col] = v1;
        }
    }
}

// ===========================================================================
// Flash attention, mma.sync tf32 + cp.async 2-stage K/V pipeline.
// Block = 128 q rows x one (b,h). 8 warps x 16 q rows. kv tiles of 64.
// Smem (floats): K[2] @ 0 / 4352 (64x68), V[2] @ 8704 / 13312 (64x72, natural
// [kv][d]; stride 72 = 8 mod 32 makes B-frag reads conflict-free).
// Total 17920 floats = 71680 B dynamic.
// ===========================================================================
#define KSTR 68
#define VSTR 72
#define FLASH_SMEM 71680

__global__ __launch_bounds__(256, 2) void flash_mma(
    const float* __restrict__ Q, const float* __restrict__ K,
    const float* __restrict__ V, float* __restrict__ Z)
{
    extern __shared__ __align__(16) float smemf[];
    const unsigned sbase = smem_u32(smemf);

    const int tid = threadIdx.x;
    const int wid = tid >> 5, lane = tid & 31;
    const int g = lane >> 2, tig = lane & 3;
    const int qt = gridDim.x - 1 - blockIdx.x;       // heavy tiles first
    const int bh = blockIdx.y;
    const int b = bh >> 4, h = bh & 15;
    const size_t base = ((size_t)b * SEQ * NH + h) * DH;
    const int qrow0 = qt * 128 + wid * 16;

    const int srow = tid >> 2;          // staging row 0..63
    const int sc16 = (tid & 3) * 16;    // staging col group (16 floats)

    // ---- Q -> register A-fragments (scale folded; stage via K buf0) ----
    unsigned aq[8][4];
    #pragma unroll
    for (int pass = 0; pass < 2; pass++) {
        const int qsrow = qt * 128 + pass * 64 + srow;
        #pragma unroll
        for (int i = 0; i < 4; i++) {
            float4 qv = *(const float4*)&Q[base + (size_t)qsrow * DM + sc16 + 4 * i];
            float4 sv = { qv.x * 0.125f, qv.y * 0.125f, qv.z * 0.125f, qv.w * 0.125f };
            *(float4*)&smemf[srow * KSTR + sc16 + 4 * i] = sv;
        }
        __syncthreads();
        if ((wid >> 2) == pass) {
            const int r = (wid & 3) * 16 + g;
            #pragma unroll
            for (int kk = 0; kk < 8; kk++) {
                aq[kk][0] = f2tf32(smemf[r * KSTR + kk * 8 + tig]);
                aq[kk][1] = f2tf32(smemf[(r + 8) * KSTR + kk * 8 + tig]);
                aq[kk][2] = f2tf32(smemf[r * KSTR + kk * 8 + tig + 4]);
                aq[kk][3] = f2tf32(smemf[(r + 8) * KSTR + kk * 8 + tig + 4]);
            }
        }
        __syncthreads();
    }

    float m0 = -1e30f, m1 = -1e30f, l0 = 0.f, l1 = 0.f;
    float oacc[8][4];
    #pragma unroll
    for (int nt = 0; nt < 8; nt++)
        #pragma unroll
        for (int i = 0; i < 4; i++) oacc[nt][i] = 0.f;

    const unsigned s1 = (lane & 28) | (tig >> 1);
    const unsigned s2 = s1 + 2;
    const int NKT = 2 * qt + 2;

    const unsigned kDst = sbase + (srow * KSTR + sc16) * 4;
    const unsigned vDst = sbase + (8704 + srow * VSTR + sc16) * 4;

    auto stage = [&](int kt, int buf) {
        const int ktb = kt * 64;
        const float* kp = K + base + (size_t)(ktb + srow) * DM + sc16;
        const float* vp = V + base + (size_t)(ktb + srow) * DM + sc16;
        const unsigned kd = kDst + buf * (4352 * 4);
        const unsigned vd = vDst + buf * (4608 * 4);
        #pragma unroll
        for (int f = 0; f < 4; f++) { cp16(kd + f * 16, kp + f * 4); cp16(vd + f * 16, vp + f * 4); }
    };

    stage(0, 0); CP_COMMIT();

    for (int kt = 0; kt < NKT; kt++) {
        if (kt + 1 < NKT) { stage(kt + 1, (kt + 1) & 1); CP_COMMIT(); CP_WAIT(1); }
        else              { CP_WAIT(0); }
        __syncthreads();

        const int ktb = kt * 64;
        if (ktb <= qrow0 + 15) {
            const float* kbuf = smemf + (kt & 1) * 4352;
            const float* vbuf = smemf + 8704 + (kt & 1) * 4608;

            // ---- S = Q K^T ----
            float sacc[8][4];
            #pragma unroll
            for (int nt = 0; nt < 8; nt++)
                #pragma unroll
                for (int i = 0; i < 4; i++) sacc[nt][i] = 0.f;

            #pragma unroll
            for (int kk = 0; kk < 8; kk++) {
                unsigned bf[8][2];
                #pragma unroll
                for (int nt = 0; nt < 8; nt++) {
                    bf[nt][0] = f2tf32(kbuf[(nt * 8 + g) * KSTR + kk * 8 + tig]);
                    bf[nt][1] = f2tf32(kbuf[(nt * 8 + g) * KSTR + kk * 8 + tig + 4]);
                }
                #pragma unroll
                for (int nt = 0; nt < 8; nt++)
                    mma_tf32(sacc[nt], aq[kk], bf[nt]);
            }

            // ---- causal mask (diagonal tiles only) ----
            if (ktb + 63 > qrow0) {
                #pragma unroll
                for (int nt = 0; nt < 8; nt++) {
                    const int kv0 = ktb + nt * 8 + 2 * tig;
                    if (kv0     > qrow0 + g)     sacc[nt][0] = -1e30f;
                    if (kv0 + 1 > qrow0 + g)     sacc[nt][1] = -1e30f;
                    if (kv0     > qrow0 + g + 8) sacc[nt][2] = -1e30f;
                    if (kv0 + 1 > qrow0 + g + 8) sacc[nt][3] = -1e30f;
                }
            }

            // ---- online softmax ----
            float rm0 = -1e30f, rm1 = -1e30f;
            #pragma unroll
            for (int nt = 0; nt < 8; nt++) {
                rm0 = fmaxf(rm0, fmaxf(sacc[nt][0], sacc[nt][1]));
                rm1 = fmaxf(rm1, fmaxf(sacc[nt][2], sacc[nt][3]));
            }
            rm0 = fmaxf(rm0, __shfl_xor_sync(0xffffffffu, rm0, 1));
            rm0 = fmaxf(rm0, __shfl_xor_sync(0xffffffffu, rm0, 2));
            rm1 = fmaxf(rm1, __shfl_xor_sync(0xffffffffu, rm1, 1));
            rm1 = fmaxf(rm1, __shfl_xor_sync(0xffffffffu, rm1, 2));
            const float mn0 = fmaxf(m0, rm0), mn1 = fmaxf(m1, rm1);
            const float al0 = __expf(m0 - mn0), al1 = __expf(m1 - mn1);
            float rs0 = 0.f, rs1 = 0.f;
            #pragma unroll
            for (int nt = 0; nt < 8; nt++) {
                sacc[nt][0] = __expf(sacc[nt][0] - mn0); rs0 += sacc[nt][0];
                sacc[nt][1] = __expf(sacc[nt][1] - mn0); rs0 += sacc[nt][1];
                sacc[nt][2] = __expf(sacc[nt][2] - mn1); rs1 += sacc[nt][2];
                sacc[nt][3] = __expf(sacc[nt][3] - mn1); rs1 += sacc[nt][3];
            }
            rs0 += __shfl_xor_sync(0xffffffffu, rs0, 1);
            rs0 += __shfl_xor_sync(0xffffffffu, rs0, 2);
            rs1 += __shfl_xor_sync(0xffffffffu, rs1, 1);
            rs1 += __shfl_xor_sync(0xffffffffu, rs1, 2);
            l0 = l0 * al0 + rs0;  l1 = l1 * al1 + rs1;
            m0 = mn0;             m1 = mn1;
            #pragma unroll
            for (int nt = 0; nt < 8; nt++) {
                oacc[nt][0] *= al0; oacc[nt][1] *= al0;
                oacc[nt][2] *= al1; oacc[nt][3] *= al1;
            }

            // ---- O += P V  (P fragment via shfl; V natural [kv][d]) ----
            #pragma unroll
            for (int kk = 0; kk < 8; kk++) {
                const float c0a = __shfl_sync(0xffffffffu, sacc[kk][0], s1);
                const float c1a = __shfl_sync(0xffffffffu, sacc[kk][1], s1);
                const float c2a = __shfl_sync(0xffffffffu, sacc[kk][2], s1);
                const float c3a = __shfl_sync(0xffffffffu, sacc[kk][3], s1);
                const float c0b = __shfl_sync(0xffffffffu, sacc[kk][0], s2);
                const float c1b = __shfl_sync(0xffffffffu, sacc[kk][1], s2);
                const float c2b = __shfl_sync(0xffffffffu, sacc[kk][2], s2);
                const float c3b = __shfl_sync(0xffffffffu, sacc[kk][3], s2);
                unsigned ap[4];
                ap[0] = f2tf32((tig & 1) ? c1a : c0a);
                ap[1] = f2tf32((tig & 1) ? c3a : c2a);
                ap[2] = f2tf32((tig & 1) ? c1b : c0b);
                ap[3] = f2tf32((tig & 1) ? c3b : c2b);
                unsigned bf[8][2];
                #pragma unroll
                for (int nt = 0; nt < 8; nt++) {
                    bf[nt][0] = f2tf32(vbuf[(kk * 8 + tig) * VSTR + nt * 8 + g]);
                    bf[nt][1] = f2tf32(vbuf[(kk * 8 + tig + 4) * VSTR + nt * 8 + g]);
                }
                #pragma unroll
                for (int nt = 0; nt < 8; nt++)
                    mma_tf32(oacc[nt], ap, bf[nt]);
            }
        }
        __syncthreads();
    }

    // ---- normalize + write z[b, s, h, d] ----
    const float i0 = 1.f / l0, i1 = 1.f / l1;
    #pragma unroll
    for (int nt = 0; nt < 8; nt++) {
        const int col = nt * 8 + 2 * tig;
        const int row = qrow0 + g;
        float2 v0 = { oacc[nt][0] * i0, oacc[nt][1] * i0 };
        float2 v1 = { oacc[nt][2] * i1, oacc[nt][3] * i1 };
        *(float2*)&Z[base + (size_t)row * DM + col] = v0;
        *(float2*)&Z[base + (size_t)(row + 8) * DM + col] = v1;
    }
}

// ---------------------------------------------------------------------------

extern "C" void kernel_launch(void* const* d_in, const int* in_sizes, int n_in,
                              void* d_out, int out_size)
{
    const float* x  = (const float*)d_in[0];
    const float* WQ = (const float*)d_in[1];
    const float* WK = (const float*)d_in[2];
    const float* WV = (const float*)d_in[3];
    const float* WO = (const float*)d_in[4];
    const float* bQ = (const float*)d_in[5];
    const float* bK = (const float*)d_in[6];
    const float* bV = (const float*)d_in[7];
    const float* bO = (const float*)d_in[8];
    float* out = (float*)d_out;

    float *q, *k, *v, *z;
    cudaGetSymbolAddress((void**)&q, g_q);
    cudaGetSymbolAddress((void**)&k, g_k);
    cudaGetSymbolAddress((void**)&v, g_v);
    cudaGetSymbolAddress((void**)&z, g_z);

    cudaFuncSetAttribute(tc_gemm<0>, cudaFuncAttributeMaxDynamicSharedMemorySize, GEMM_SMEM);
    cudaFuncSetAttribute(tc_gemm<1>, cudaFuncAttributeMaxDynamicSharedMemorySize, GEMM_SMEM);
    cudaFuncSetAttribute(flash_mma,  cudaFuncAttributeMaxDynamicSharedMemorySize, FLASH_SMEM);

    dim3 gg(DM / BN, MTOT / BM);        // (8, 32)
    tc_gemm<1><<<gg, 256, GEMM_SMEM>>>(x, WQ, bQ, q);
    tc_gemm<1><<<gg, 256, GEMM_SMEM>>>(x, WK, bK, k);
    tc_gemm<1><<<gg, 256, GEMM_SMEM>>>(x, WV, bV, v);
    flash_mma<<<dim3(SEQ / 128, BATCH * NH), 256, FLASH_SMEM>>>(q, k, v, z);
    tc_gemm<0><<<gg, 256, GEMM_SMEM>>>(z, WO, bO, out);
}